// round 4
// baseline (speedup 1.0000x reference)
#include <cuda_runtime.h>
#include <cuda_fp16.h>
#include <cstdint>

#define N_DIM   11008
#define K_DIM   4096
#define KW      2048      // int32 words per weight row (one nibble-pair per word)
#define NCHUNK  32        // K chunks of 128 (== scale group)
#define CW      64        // int32 words per row per chunk
#define APITCH  272       // smem pitch (bytes) for A rows (256B data + pad)
#define XPITCH  272       // smem pitch (bytes) for x tokens (256B fp16 data + pad)
#define ABYTES  (128 * APITCH)          // 34816
#define XBYTES  (32  * XPITCH)          // 8704
#define BUFB    (ABYTES + XBYTES)       // 43520 per stage
#define NSTAGE  4                       // 174080 bytes total dynamic smem
#define NITER   (NCHUNK / 2)            // 16 iterations, 2 chunks each

__device__ __half g_x16[32 * K_DIM];   // fp16 copy of x (values exactly fp16-representable)

__device__ __forceinline__ void cpa16(uint32_t dst, const void* src) {
    asm volatile("cp.async.cg.shared.global [%0], [%1], 16;" :: "r"(dst), "l"(src));
}
__device__ __forceinline__ uint32_t lds32(uint32_t a) {
    uint32_t v; asm volatile("ld.shared.b32 %0, [%1];" : "=r"(v) : "r"(a)); return v;
}
// low byte of w (two nibbles) -> fp16x2 {lo_nib-8, hi_nib-8}, exact
__device__ __forceinline__ uint32_t cvt_pair(uint32_t w) {
    uint32_t p = ((w | (w << 12)) & 0x000F000Fu) | 0x64006400u;
    uint32_t r;
    asm("sub.f16x2 %0, %1, %2;" : "=r"(r) : "r"(p), "r"(0x64086408u));
    return r;
}
__device__ __forceinline__ void mma16816(float* d,
    uint32_t a0, uint32_t a1, uint32_t a2, uint32_t a3,
    uint32_t b0, uint32_t b1) {
    asm volatile(
        "mma.sync.aligned.m16n8k16.row.col.f32.f16.f16.f32 "
        "{%0,%1,%2,%3}, {%4,%5,%6,%7}, {%8,%9}, {%0,%1,%2,%3};"
        : "+f"(d[0]), "+f"(d[1]), "+f"(d[2]), "+f"(d[3])
        : "r"(a0), "r"(a1), "r"(a2), "r"(a3), "r"(b0), "r"(b1));
}

extern __shared__ char smem_raw[];

__global__ void cvt_x_kernel(const float* __restrict__ x, int n) {
    int i = blockIdx.x * blockDim.x + threadIdx.x;
    int stride = gridDim.x * blockDim.x;
    for (; i < n; i += stride) g_x16[i] = __float2half(x[i]);
}

// stage one 128-row chunk with 512 threads (4 A vectors + 1 x vector each)
__device__ __forceinline__ void stage_chunk512(uint32_t sb, int chunk, int tid, int nb,
                                               const int* __restrict__ wp) {
    uint32_t aB = sb + (uint32_t)(chunk & (NSTAGE - 1)) * BUFB;
    uint32_t xB = aB + ABYTES;
    const int* wsrc = wp + (size_t)nb * KW + chunk * CW;
    #pragma unroll
    for (int i = 0; i < 4; i++) {
        int idx = tid + i * 512;           // 2048 16B vectors: 128 rows x 16 segs
        int row = idx >> 4, seg = idx & 15;
        cpa16(aB + row * APITCH + seg * 16, wsrc + (size_t)row * KW + seg * 4);
    }
    {
        int tok = tid >> 4, seg = tid & 15; // 512 vectors: 32 tok x 16 segs
        cpa16(xB + tok * XPITCH + seg * 16,
              g_x16 + (size_t)chunk * 128 + (size_t)tok * K_DIM + seg * 8);
    }
}

__global__ void __launch_bounds__(512, 1)
w4a16_mma_kernel(const int* __restrict__ wp,
                 const float* __restrict__ sc,
                 float* __restrict__ out) {
    const int tid  = threadIdx.x;
    const int warp = tid >> 5;        // 0..15
    const int set  = warp >> 3;       // 0: even chunks, 1: odd chunks
    const int wIn  = warp & 7;        // warp within set
    const int lane = tid & 31;
    const int g = lane >> 2;          // group-of-4 id (0..7)
    const int t = lane & 3;           // thread in group (0..3)
    const int nb = blockIdx.x * 128;  // N base for this CTA

    const uint32_t sb = (uint32_t)__cvta_generic_to_shared(smem_raw);

    float acc[4][4];
    #pragma unroll
    for (int i = 0; i < 4; i++)
        #pragma unroll
        for (int j = 0; j < 4; j++) acc[i][j] = 0.0f;

    // prologue: two groups of two chunks in flight
    stage_chunk512(sb, 0, tid, nb, wp);
    stage_chunk512(sb, 1, tid, nb, wp);
    asm volatile("cp.async.commit_group;" ::: "memory");
    stage_chunk512(sb, 2, tid, nb, wp);
    stage_chunk512(sb, 3, tid, nb, wp);
    asm volatile("cp.async.commit_group;" ::: "memory");

    const size_t scRow0 = (size_t)(nb + wIn * 16 + g) * NCHUNK;
    const size_t scRow1 = scRow0 + 8 * NCHUNK;

    for (int i = 0; i < NITER; i++) {
        // wait until only the newest group is outstanding -> chunks 2i,2i+1 ready
        asm volatile("cp.async.wait_group 1;" ::: "memory");
        __syncthreads();

        const int c = 2 * i + set;             // this warp-set's chunk
        const uint32_t aB = sb + (uint32_t)(c & (NSTAGE - 1)) * BUFB;
        const uint32_t xB = aB + ABYTES;
        const uint32_t aAddr0 = aB + (wIn * 16 + g) * APITCH + t * 4;
        const uint32_t aAddr1 = aAddr0 + 8 * APITCH;

        float s0 = sc[scRow0 + c];
        float s1 = sc[scRow1 + c];

        float dd[4][4];
        #pragma unroll
        for (int a = 0; a < 4; a++)
            #pragma unroll
            for (int b = 0; b < 4; b++) dd[a][b] = 0.0f;

        #pragma unroll
        for (int s = 0; s < 8; s++) {
            uint32_t w00 = lds32(aAddr0 + s * 32);        // word 8s+t   -> k = 16s+2t
            uint32_t w10 = lds32(aAddr1 + s * 32);
            uint32_t w01 = lds32(aAddr0 + s * 32 + 16);   // word 8s+t+4 -> k = 16s+2t+8
            uint32_t w11 = lds32(aAddr1 + s * 32 + 16);
            uint32_t A0 = cvt_pair(w00);
            uint32_t A1 = cvt_pair(w10);
            uint32_t A2 = cvt_pair(w01);
            uint32_t A3 = cvt_pair(w11);
            #pragma unroll
            for (int q = 0; q < 4; q++) {  // token groups of 8
                uint32_t bbase = xB + (8 * q + g) * XPITCH + s * 32 + t * 4;
                uint32_t b0 = lds32(bbase);
                uint32_t b1 = lds32(bbase + 16);
                mma16816(dd[q], A0, A1, A2, A3, b0, b1);
            }
        }

        #pragma unroll
        for (int q = 0; q < 4; q++) {
            acc[q][0] += dd[q][0] * s0;
            acc[q][1] += dd[q][1] * s0;
            acc[q][2] += dd[q][2] * s1;
            acc[q][3] += dd[q][3] * s1;
        }

        // buffers for chunks 2i,2i+1 now free; stage chunks 2i+4,2i+5 into them
        __syncthreads();
        if (i + 2 < NITER) {
            stage_chunk512(sb, 2 * i + 4, tid, nb, wp);
            stage_chunk512(sb, 2 * i + 5, tid, nb, wp);
        }
        asm volatile("cp.async.commit_group;" ::: "memory");  // uniform group count
    }

    // merge the two warp-sets' partial accumulators via smem
    asm volatile("cp.async.wait_group 0;" ::: "memory");
    __syncthreads();
    float4* red = (float4*)smem_raw;   // 256 threads x 4 float4 = 16KB
    if (set == 1) {
        int base = (tid - 256) * 4;
        #pragma unroll
        for (int q = 0; q < 4; q++)
            red[base + q] = make_float4(acc[q][0], acc[q][1], acc[q][2], acc[q][3]);
    }
    __syncthreads();
    if (set == 0) {
        int base = tid * 4;
        const int n0 = nb + wIn * 16 + g;
        #pragma unroll
        for (int q = 0; q < 4; q++) {
            float4 v = red[base + q];
            float r0 = acc[q][0] + v.x;
            float r1 = acc[q][1] + v.y;
            float r2 = acc[q][2] + v.z;
            float r3 = acc[q][3] + v.w;
            int m0 = 8 * q + 2 * t;
            // fp32 out, rounded through fp16 to match reference astype(float16)
            out[(size_t)m0       * N_DIM + n0    ] = __half2float(__float2half(r0));
            out[(size_t)(m0 + 1) * N_DIM + n0    ] = __half2float(__float2half(r1));
            out[(size_t)m0       * N_DIM + n0 + 8] = __half2float(__float2half(r2));
            out[(size_t)(m0 + 1) * N_DIM + n0 + 8] = __half2float(__float2half(r3));
        }
    }
}

extern "C" void kernel_launch(void* const* d_in, const int* in_sizes, int n_in,
                              void* d_out, int out_size) {
    const float* x  = (const float*)d_in[0];
    const int*   wp = (const int*)d_in[1];
    const float* sc = (const float*)d_in[2];
    float*       out = (float*)d_out;

    cvt_x_kernel<<<128, 256>>>(x, 32 * K_DIM);

    cudaFuncSetAttribute(w4a16_mma_kernel,
                         cudaFuncAttributeMaxDynamicSharedMemorySize, NSTAGE * BUFB);
    w4a16_mma_kernel<<<N_DIM / 128, 512, NSTAGE * BUFB>>>(wp, sc, out);
}

// round 5
// speedup vs baseline: 1.0585x; 1.0585x over previous
#include <cuda_runtime.h>
#include <cuda_fp16.h>
#include <cstdint>

#define N_DIM   11008
#define K_DIM   4096
#define KW      2048      // int32 words per weight row (one nibble-pair per word)
#define NCHUNK  32        // K chunks of 128 (== scale group)
#define CW      64        // int32 words per row per chunk
#define APITCH  272       // smem pitch (bytes) for A rows
#define XPITCH  272       // smem pitch (bytes) for x tokens
#define ABYTES  (128 * APITCH)          // 34816
#define XBYTES  (32  * XPITCH)          // 8704
#define BUFB    (ABYTES + XBYTES)       // 43520 per stage
#define NSTAGE  4
#define MBAR_OFF (NSTAGE * BUFB)        // 174080
#define SMEM_TOTAL (MBAR_OFF + 64)      // 8 mbarriers
#define NCONS   256                     // consumer threads (warps 0-7)
#define NPROD   128                     // producer threads (warps 8-11)

__device__ __half g_x16[32 * K_DIM];   // fp16 copy of x (values exactly fp16-representable)

__device__ __forceinline__ void cpa16(uint32_t dst, const void* src) {
    asm volatile("cp.async.cg.shared.global [%0], [%1], 16;" :: "r"(dst), "l"(src));
}
__device__ __forceinline__ uint32_t lds32(uint32_t a) {
    uint32_t v; asm volatile("ld.shared.b32 %0, [%1];" : "=r"(v) : "r"(a)); return v;
}
__device__ __forceinline__ uint32_t cvt_pair(uint32_t w) {
    uint32_t p = ((w | (w << 12)) & 0x000F000Fu) | 0x64006400u;
    uint32_t r;
    asm("sub.f16x2 %0, %1, %2;" : "=r"(r) : "r"(p), "r"(0x64086408u));
    return r;
}
__device__ __forceinline__ void mma16816(float* d,
    uint32_t a0, uint32_t a1, uint32_t a2, uint32_t a3,
    uint32_t b0, uint32_t b1) {
    asm volatile(
        "mma.sync.aligned.m16n8k16.row.col.f32.f16.f16.f32 "
        "{%0,%1,%2,%3}, {%4,%5,%6,%7}, {%8,%9}, {%0,%1,%2,%3};"
        : "+f"(d[0]), "+f"(d[1]), "+f"(d[2]), "+f"(d[3])
        : "r"(a0), "r"(a1), "r"(a2), "r"(a3), "r"(b0), "r"(b1));
}
__device__ __forceinline__ void mbar_init(uint32_t a, uint32_t cnt) {
    asm volatile("mbarrier.init.shared.b64 [%0], %1;" :: "r"(a), "r"(cnt) : "memory");
}
__device__ __forceinline__ void mbar_arrive(uint32_t a) {
    asm volatile("mbarrier.arrive.shared.b64 _, [%0];" :: "r"(a) : "memory");
}
__device__ __forceinline__ void mbar_wait(uint32_t a, uint32_t parity) {
    asm volatile(
        "{\n\t.reg .pred P;\n\t"
        "LAB_%=:\n\t"
        "mbarrier.try_wait.parity.acquire.cta.shared::cta.b64 P, [%0], %1, 0x989680;\n\t"
        "@!P bra LAB_%=;\n\t}"
        :: "r"(a), "r"(parity) : "memory");
}

extern __shared__ char smem_raw[];

__global__ void cvt_x_kernel(const float* __restrict__ x, int n) {
    int i = blockIdx.x * blockDim.x + threadIdx.x;
    int stride = gridDim.x * blockDim.x;
    for (; i < n; i += stride) g_x16[i] = __float2half(x[i]);
}

// stage one chunk with 128 producer threads: 16 A vectors + 4 x vectors each
__device__ __forceinline__ void stage_chunk_p(uint32_t sb, int chunk, int ptid, int nb,
                                              const int* __restrict__ wp) {
    uint32_t aB = sb + (uint32_t)(chunk & (NSTAGE - 1)) * BUFB;
    uint32_t xB = aB + ABYTES;
    const int* wsrc = wp + (size_t)nb * KW + chunk * CW;
    #pragma unroll
    for (int i = 0; i < 16; i++) {
        int idx = ptid + i * 128;          // 2048 16B vectors: 128 rows x 16 segs
        int row = idx >> 4, seg = idx & 15;
        cpa16(aB + row * APITCH + seg * 16, wsrc + (size_t)row * KW + seg * 4);
    }
    #pragma unroll
    for (int i = 0; i < 4; i++) {
        int idx = ptid + i * 128;          // 512 vectors: 32 tok x 16 segs
        int tok = idx >> 4, seg = idx & 15;
        cpa16(xB + tok * XPITCH + seg * 16,
              g_x16 + (size_t)chunk * 128 + (size_t)tok * K_DIM + seg * 8);
    }
}

__global__ void __launch_bounds__(384, 1)
w4a16_mma_kernel(const int* __restrict__ wp,
                 const float* __restrict__ sc,
                 float* __restrict__ out) {
    const int tid  = threadIdx.x;
    const int nb   = blockIdx.x * 128;
    const uint32_t sb = (uint32_t)__cvta_generic_to_shared(smem_raw);
    const uint32_t mb = sb + MBAR_OFF;   // full[0..3] at +0..+24, empty[0..3] at +32..+56

    if (tid == 0) {
        #pragma unroll
        for (int s = 0; s < NSTAGE; s++) {
            mbar_init(mb + s * 8, NPROD);           // full[s]
            mbar_init(mb + 32 + s * 8, NCONS);      // empty[s]
        }
    }
    __syncthreads();

    if (tid >= NCONS) {
        // ================== PRODUCER (warps 8-11) ==================
        const int ptid = tid - NCONS;
        #pragma unroll 1
        for (int c = 0; c < NCHUNK; c++) {
            const int s = c & (NSTAGE - 1);
            const uint32_t ph = 1u ^ ((c >> 2) & 1);    // empty-wait parity
            mbar_wait(mb + 32 + s * 8, ph);
            stage_chunk_p(sb, c, ptid, nb, wp);
            asm volatile("cp.async.commit_group;" ::: "memory");
            if (c >= 3) {
                asm volatile("cp.async.wait_group 3;" ::: "memory");
                mbar_arrive(mb + ((c - 3) & (NSTAGE - 1)) * 8);
            }
        }
        asm volatile("cp.async.wait_group 2;" ::: "memory");
        mbar_arrive(mb + 1 * 8);   // chunk 29
        asm volatile("cp.async.wait_group 1;" ::: "memory");
        mbar_arrive(mb + 2 * 8);   // chunk 30
        asm volatile("cp.async.wait_group 0;" ::: "memory");
        mbar_arrive(mb + 3 * 8);   // chunk 31
        return;
    }

    // ================== CONSUMER (warps 0-7) ==================
    const int warp = tid >> 5;
    const int lane = tid & 31;
    const int g = lane >> 2;
    const int t = lane & 3;

    float acc[4][4];
    #pragma unroll
    for (int i = 0; i < 4; i++)
        #pragma unroll
        for (int j = 0; j < 4; j++) acc[i][j] = 0.0f;

    const size_t scRow0 = (size_t)(nb + warp * 16 + g) * NCHUNK;
    const size_t scRow1 = scRow0 + 8 * NCHUNK;

    #pragma unroll 1
    for (int c = 0; c < NCHUNK; c++) {
        const int s = c & (NSTAGE - 1);
        mbar_wait(mb + s * 8, (c >> 2) & 1);

        float s0 = sc[scRow0 + c];
        float s1 = sc[scRow1 + c];

        const uint32_t aB = sb + (uint32_t)s * BUFB;
        const uint32_t xB = aB + ABYTES;
        const uint32_t aAddr0 = aB + (warp * 16 + g) * APITCH + t * 4;
        const uint32_t aAddr1 = aAddr0 + 8 * APITCH;

        float dd[4][4];
        #pragma unroll
        for (int a = 0; a < 4; a++)
            #pragma unroll
            for (int b = 0; b < 4; b++) dd[a][b] = 0.0f;

        #pragma unroll
        for (int ss = 0; ss < 8; ss++) {
            uint32_t w00 = lds32(aAddr0 + ss * 32);        // word 8s+t   -> k = 16s+2t
            uint32_t w10 = lds32(aAddr1 + ss * 32);
            uint32_t w01 = lds32(aAddr0 + ss * 32 + 16);   // word 8s+t+4 -> k = 16s+2t+8
            uint32_t w11 = lds32(aAddr1 + ss * 32 + 16);
            uint32_t A0 = cvt_pair(w00);
            uint32_t A1 = cvt_pair(w10);
            uint32_t A2 = cvt_pair(w01);
            uint32_t A3 = cvt_pair(w11);
            #pragma unroll
            for (int q = 0; q < 4; q++) {
                uint32_t bbase = xB + (8 * q + g) * XPITCH + ss * 32 + t * 4;
                uint32_t b0 = lds32(bbase);
                uint32_t b1 = lds32(bbase + 16);
                mma16816(dd[q], A0, A1, A2, A3, b0, b1);
            }
        }

        #pragma unroll
        for (int q = 0; q < 4; q++) {
            acc[q][0] += dd[q][0] * s0;
            acc[q][1] += dd[q][1] * s0;
            acc[q][2] += dd[q][2] * s1;
            acc[q][3] += dd[q][3] * s1;
        }

        mbar_arrive(mb + 32 + s * 8);   // buffer s free
    }

    // writeback (fp32 out, rounded through fp16 to match reference astype(float16))
    const int n0 = nb + warp * 16 + g;
    #pragma unroll
    for (int q = 0; q < 4; q++) {
        int m0 = 8 * q + 2 * t;
        out[(size_t)m0       * N_DIM + n0    ] = __half2float(__float2half(acc[q][0]));
        out[(size_t)(m0 + 1) * N_DIM + n0    ] = __half2float(__float2half(acc[q][1]));
        out[(size_t)m0       * N_DIM + n0 + 8] = __half2float(__float2half(acc[q][2]));
        out[(size_t)(m0 + 1) * N_DIM + n0 + 8] = __half2float(__float2half(acc[q][3]));
    }
}

extern "C" void kernel_launch(void* const* d_in, const int* in_sizes, int n_in,
                              void* d_out, int out_size) {
    const float* x  = (const float*)d_in[0];
    const int*   wp = (const int*)d_in[1];
    const float* sc = (const float*)d_in[2];
    float*       out = (float*)d_out;

    cvt_x_kernel<<<128, 256>>>(x, 32 * K_DIM);

    cudaFuncSetAttribute(w4a16_mma_kernel,
                         cudaFuncAttributeMaxDynamicSharedMemorySize, SMEM_TOTAL);
    w4a16_mma_kernel<<<N_DIM / 128, 384, SMEM_TOTAL>>>(wp, sc, out);
}